// round 2
// baseline (speedup 1.0000x reference)
#include <cuda_runtime.h>
#include <math.h>

#define BB 8
#define LL 20
#define ND 2048           // N
#define FF 64             // F
#define NSQ (ND*ND)       // 4194304 = 2^22

// ---------------- scratch (static device, no allocation) ----------------
__device__ double g_m2[BB*LL*FF];         // per (b,l,f) mean over N (double)
__device__ int    g_k[BB];
__device__ float  g_Xn [BB*ND*FF];        // normalized x_last, [b][n][f]
__device__ float  g_XnT[BB*FF*ND];        // transposed,        [b*64+f][n]
__device__ float  g_Tmat[BB*FF*ND];       // t = Xn^T @ prior,  [b*64+f][k]
__device__ unsigned g_hist1[BB*4096];
__device__ unsigned g_hist2[BB*4096];
__device__ unsigned g_hist3[BB*256];
__device__ unsigned g_bin1[BB], g_bin2[BB];
__device__ unsigned g_above1[BB], g_above2[BB];
__device__ unsigned g_thresh[BB];

__device__ __forceinline__ unsigned f2o(float f) {
    unsigned u = __float_as_uint(f);
    return (u & 0x80000000u) ? ~u : (u | 0x80000000u);
}

// ---------------- zero histograms ----------------
__global__ void zero_hists_kernel() {
    int tot = BB*4096*2 + BB*256;
    for (int i = blockIdx.x*blockDim.x + threadIdx.x; i < tot; i += gridDim.x*blockDim.x) {
        if (i < BB*4096)        g_hist1[i] = 0;
        else if (i < 2*BB*4096) g_hist2[i - BB*4096] = 0;
        else                    g_hist3[i - 2*BB*4096] = 0;
    }
}

// ---------------- m2 = mean over N (double accumulation) ----------------
__global__ __launch_bounds__(256) void mean_kernel(const float* __restrict__ x_seq) {
    int bl = blockIdx.x;                    // 0..B*L-1
    int f = threadIdx.x & 63, j = threadIdx.x >> 6;   // j in 0..3
    const float* base = x_seq + (size_t)bl * ND * FF;
    double s = 0.0;
    int n0 = j * 512;
    for (int n = n0; n < n0 + 512; n++) s += (double)base[(size_t)n * FF + f];
    __shared__ double p[4][64];
    p[j][f] = s;
    __syncthreads();
    if (j == 0) {
        double t = (p[0][f] + p[1][f]) + (p[2][f] + p[3][f]);
        g_m2[bl * FF + f] = t * (1.0 / ND);
    }
}

// ---------------- tiny conv net -> k[b]  (all double) ----------------
__global__ __launch_bounds__(256) void net_kernel(
    const float* __restrict__ w1, const float* __restrict__ b1,
    const float* __restrict__ w2, const float* __restrict__ b2,
    const float* __restrict__ w3, const float* __restrict__ b3,
    const float* __restrict__ w4, const float* __restrict__ b4,
    const float* __restrict__ wout, const float* __restrict__ bout)
{
    __shared__ double sm[22][66];      // zero-padded (L+2) x (F+2)
    __shared__ double wsum[32][8];     // per-warp partials
    int tid = threadIdx.x;
    int lane = tid & 31, warp = tid >> 5;

    for (int b = 0; b < BB; b++) {
        for (int i = tid; i < 22*66; i += 256) ((double*)sm)[i] = 0.0;
        __syncthreads();
        for (int i = tid; i < LL*FF; i += 256) {
            int h = i / FF, w = i % FF;
            sm[h+1][w+1] = g_m2[(b*LL + h)*FF + w];
        }
        __syncthreads();

        double s[32];
        #pragma unroll
        for (int q = 0; q < 32; q++) s[q] = 0.0;

        for (int i = tid; i < LL*FF; i += 256) {
            int h = i / FF + 1, w = i % FF + 1;
            double c   = sm[h][w];
            double lft = sm[h][w-1], rgt = sm[h][w+1];
            double up  = sm[h-1][w], dn  = sm[h+1][w];
            double ul  = sm[h-1][w-1], ur = sm[h-1][w+1];
            double dl  = sm[h+1][w-1], dr = sm[h+1][w+1];
            #pragma unroll
            for (int ch = 0; ch < 8; ch++) {
                double v1 = (double)w1[ch]*c + (double)b1[ch];
                double v2 = (double)w2[ch*3+0]*lft + (double)w2[ch*3+1]*c + (double)w2[ch*3+2]*rgt + (double)b2[ch];
                double v3 = (double)w3[ch*3+0]*up  + (double)w3[ch*3+1]*c + (double)w3[ch*3+2]*dn  + (double)b3[ch];
                double v4 = (double)w4[ch*9+0]*ul + (double)w4[ch*9+1]*up + (double)w4[ch*9+2]*ur
                          + (double)w4[ch*9+3]*lft+ (double)w4[ch*9+4]*c  + (double)w4[ch*9+5]*rgt
                          + (double)w4[ch*9+6]*dl + (double)w4[ch*9+7]*dn + (double)w4[ch*9+8]*dr + (double)b4[ch];
                s[ch]      += 0.5*v1*(1.0 + erf(v1*0.7071067811865475244));
                s[8  + ch] += 0.5*v2*(1.0 + erf(v2*0.7071067811865475244));
                s[16 + ch] += 0.5*v3*(1.0 + erf(v3*0.7071067811865475244));
                s[24 + ch] += 0.5*v4*(1.0 + erf(v4*0.7071067811865475244));
            }
        }
        // deterministic warp-tree reduction
        #pragma unroll
        for (int q = 0; q < 32; q++) {
            double v = s[q];
            #pragma unroll
            for (int o = 16; o; o >>= 1) v += __shfl_down_sync(0xffffffffu, v, o);
            if (lane == 0) wsum[q][warp] = v;
        }
        __syncthreads();
        if (tid == 0) {
            double logit = (double)bout[0];
            for (int q = 0; q < 32; q++) {
                double t = 0.0;
                for (int w = 0; w < 8; w++) t += wsum[q][w];   // fixed order
                logit += (t * (1.0/(LL*FF))) * (double)wout[q];
            }
            double sig  = 1.0 / (1.0 + exp(-logit));
            double keep = 0.2 * sig;
            if (keep < 0.02) keep = 0.02;
            if (keep > 1.0)  keep = 1.0;
            // replicate reference fp32 quantization: fp32(keep) * fp32(NSQ), ceil
            float kf = __fmul_rn((float)keep, 4194304.0f);
            int k = (int)ceilf(kf);
            if (k < 1) k = 1;
            if (k > NSQ) k = NSQ;
            g_k[b] = k;
        }
        __syncthreads();
    }
}

// ---------------- normalize last slice (double), write Xn and XnT ----------------
__global__ __launch_bounds__(256) void norm_kernel(const float* __restrict__ x_seq) {
    int warp = (blockIdx.x*blockDim.x + threadIdx.x) >> 5;
    int lane = threadIdx.x & 31;
    if (warp >= BB*ND) return;
    int b = warp >> 11, n = warp & (ND-1);
    const float* row = x_seq + ((size_t)(b*LL + (LL-1)) * ND + n) * FF;
    float v0 = row[lane], v1 = row[lane + 32];
    double ss = (double)v0*(double)v0 + (double)v1*(double)v1;
    #pragma unroll
    for (int o = 16; o; o >>= 1) ss += __shfl_xor_sync(0xffffffffu, ss, o);
    double d = sqrt(ss);
    if (d < 1e-12) d = 1e-12;
    float y0 = (float)((double)v0 / d), y1 = (float)((double)v1 / d);
    size_t rb = (size_t)(b*ND + n) * FF;
    g_Xn[rb + lane]      = y0;
    g_Xn[rb + lane + 32] = y1;
    g_XnT[(size_t)(b*FF + lane)      * ND + n] = y0;
    g_XnT[(size_t)(b*FF + lane + 32) * ND + n] = y1;
}

// ---------------- GEMM1: Tmat(512x2048) = XnT(512x2048) @ prior(2048x2048) ----
// per-BK local accumulator + Kahan-compensated flush (accuracy-critical)
__global__ __launch_bounds__(256) void gemm1_kernel(const float* __restrict__ Bm) {
    const int BM = 64, BN = 128, BK = 16;
    __shared__ float As[BK][BM+1];
    __shared__ __align__(16) float Bs[BK][BN];
    int tx = threadIdx.x & 15, ty = threadIdx.x >> 4;
    int bm0 = blockIdx.y * BM, bn0 = blockIdx.x * BN;
    float acc[4][8], comp[4][8];
    #pragma unroll
    for (int i = 0; i < 4; i++)
        #pragma unroll
        for (int j = 0; j < 8; j++) { acc[i][j] = 0.f; comp[i][j] = 0.f; }

    for (int k0 = 0; k0 < ND; k0 += BK) {
        #pragma unroll
        for (int r = 0; r < 4; r++) {
            int idx = threadIdx.x + r*256, m = idx >> 4, kk = idx & 15;
            As[kk][m] = g_XnT[(size_t)(bm0 + m) * ND + k0 + kk];
        }
        #pragma unroll
        for (int r = 0; r < 8; r++) {
            int idx = threadIdx.x + r*256, kk = idx >> 7, col = idx & 127;
            Bs[kk][col] = Bm[(size_t)(k0 + kk) * ND + bn0 + col];
        }
        __syncthreads();
        float loc[4][8];
        #pragma unroll
        for (int i = 0; i < 4; i++)
            #pragma unroll
            for (int j = 0; j < 8; j++) loc[i][j] = 0.f;
        #pragma unroll
        for (int kk = 0; kk < BK; kk++) {
            float a0 = As[kk][ty*4+0], a1 = As[kk][ty*4+1];
            float a2 = As[kk][ty*4+2], a3 = As[kk][ty*4+3];
            float4 q0 = *reinterpret_cast<const float4*>(&Bs[kk][tx*8]);
            float4 q1 = *reinterpret_cast<const float4*>(&Bs[kk][tx*8+4]);
            float bb[8] = {q0.x,q0.y,q0.z,q0.w,q1.x,q1.y,q1.z,q1.w};
            #pragma unroll
            for (int j = 0; j < 8; j++) {
                loc[0][j] = __fmaf_rn(a0, bb[j], loc[0][j]);
                loc[1][j] = __fmaf_rn(a1, bb[j], loc[1][j]);
                loc[2][j] = __fmaf_rn(a2, bb[j], loc[2][j]);
                loc[3][j] = __fmaf_rn(a3, bb[j], loc[3][j]);
            }
        }
        // Kahan flush: acc += loc with compensation
        #pragma unroll
        for (int i = 0; i < 4; i++)
            #pragma unroll
            for (int j = 0; j < 8; j++) {
                float y = __fadd_rn(loc[i][j], -comp[i][j]);
                float t = __fadd_rn(acc[i][j], y);
                comp[i][j] = __fadd_rn(__fadd_rn(t, -acc[i][j]), -y);
                acc[i][j] = t;
            }
        __syncthreads();
    }
    #pragma unroll
    for (int i = 0; i < 4; i++)
        #pragma unroll
        for (int j = 0; j < 8; j++)
            g_Tmat[(size_t)(bm0 + ty*4 + i) * ND + bn0 + tx*8 + j] = acc[i][j];
}

// ---------------- GEMM2: a_b(2048x2048) = Xn_b(2048x64) @ t_b(64x2048) ------
// per-BK local accumulator + flush (4 flushes over K=64)
__global__ __launch_bounds__(256) void gemm2_kernel(float* __restrict__ outA) {
    const int BM = 128, BN = 128, BK = 16;
    __shared__ float As[BK][BM+1];
    __shared__ __align__(16) float Bs[BK][BN];
    int b = blockIdx.z;
    const float* A  = g_Xn   + (size_t)b * ND * FF;
    const float* Bmm= g_Tmat + (size_t)b * FF * ND;
    float* C = outA + (size_t)b * NSQ;
    int tx = threadIdx.x & 15, ty = threadIdx.x >> 4;
    int bm0 = blockIdx.y * BM, bn0 = blockIdx.x * BN;
    float acc[8][8];
    #pragma unroll
    for (int i = 0; i < 8; i++)
        #pragma unroll
        for (int j = 0; j < 8; j++) acc[i][j] = 0.f;

    for (int k0 = 0; k0 < FF; k0 += BK) {
        #pragma unroll
        for (int r = 0; r < 8; r++) {
            int idx = threadIdx.x + r*256, m = idx >> 4, kk = idx & 15;
            As[kk][m] = A[(size_t)(bm0 + m) * FF + k0 + kk];
        }
        #pragma unroll
        for (int r = 0; r < 8; r++) {
            int idx = threadIdx.x + r*256, kk = idx >> 7, col = idx & 127;
            Bs[kk][col] = Bmm[(size_t)(k0 + kk) * ND + bn0 + col];
        }
        __syncthreads();
        float loc[8][8];
        #pragma unroll
        for (int i = 0; i < 8; i++)
            #pragma unroll
            for (int j = 0; j < 8; j++) loc[i][j] = 0.f;
        #pragma unroll
        for (int kk = 0; kk < BK; kk++) {
            float av[8];
            #pragma unroll
            for (int i = 0; i < 8; i++) av[i] = As[kk][ty*8 + i];
            float4 q0 = *reinterpret_cast<const float4*>(&Bs[kk][tx*8]);
            float4 q1 = *reinterpret_cast<const float4*>(&Bs[kk][tx*8+4]);
            float bb[8] = {q0.x,q0.y,q0.z,q0.w,q1.x,q1.y,q1.z,q1.w};
            #pragma unroll
            for (int i = 0; i < 8; i++)
                #pragma unroll
                for (int j = 0; j < 8; j++)
                    loc[i][j] = __fmaf_rn(av[i], bb[j], loc[i][j]);
        }
        #pragma unroll
        for (int i = 0; i < 8; i++)
            #pragma unroll
            for (int j = 0; j < 8; j++)
                acc[i][j] = __fadd_rn(acc[i][j], loc[i][j]);
        __syncthreads();
    }
    #pragma unroll
    for (int i = 0; i < 8; i++)
        #pragma unroll
        for (int j = 0; j < 8; j++)
            C[(size_t)(bm0 + ty*8 + i) * ND + bn0 + tx*8 + j] = acc[i][j];
}

// ---------------- radix-select level 1 (top 12 bits) ----------------
__global__ __launch_bounds__(256) void hist1_kernel(const float* __restrict__ a) {
    __shared__ unsigned sh[4096];
    for (int i = threadIdx.x; i < 4096; i += 256) sh[i] = 0;
    __syncthreads();
    int b = blockIdx.y;
    const float4* p = reinterpret_cast<const float4*>(a + (size_t)b * NSQ) + (size_t)blockIdx.x * 8192;
    for (int i = threadIdx.x; i < 8192; i += 256) {
        float4 v = p[i];
        atomicAdd(&sh[f2o(v.x) >> 20], 1u);
        atomicAdd(&sh[f2o(v.y) >> 20], 1u);
        atomicAdd(&sh[f2o(v.z) >> 20], 1u);
        atomicAdd(&sh[f2o(v.w) >> 20], 1u);
    }
    __syncthreads();
    for (int i = threadIdx.x; i < 4096; i += 256) {
        unsigned c = sh[i];
        if (c) atomicAdd(&g_hist1[b*4096 + i], c);
    }
}

__global__ void scan1_kernel() {
    int b = threadIdx.x;
    if (b >= BB) return;
    unsigned k = (unsigned)g_k[b];
    unsigned cum = 0;
    int bin = 4095;
    for (; bin >= 0; bin--) {
        unsigned c = g_hist1[b*4096 + bin];
        if (cum + c >= k) break;
        cum += c;
    }
    if (bin < 0) bin = 0;
    g_bin1[b] = (unsigned)bin;
    g_above1[b] = cum;
}

__global__ __launch_bounds__(256) void hist2_kernel(const float* __restrict__ a) {
    const float4* a4 = reinterpret_cast<const float4*>(a);
    size_t tot = (size_t)BB * NSQ / 4;
    for (size_t i = (size_t)blockIdx.x*blockDim.x + threadIdx.x; i < tot;
         i += (size_t)gridDim.x * blockDim.x) {
        int b = (int)(i >> 20);
        unsigned bin1 = g_bin1[b];
        float4 v = a4[i];
        unsigned o;
        o = f2o(v.x); if ((o >> 20) == bin1) atomicAdd(&g_hist2[b*4096 + ((o >> 8) & 4095)], 1u);
        o = f2o(v.y); if ((o >> 20) == bin1) atomicAdd(&g_hist2[b*4096 + ((o >> 8) & 4095)], 1u);
        o = f2o(v.z); if ((o >> 20) == bin1) atomicAdd(&g_hist2[b*4096 + ((o >> 8) & 4095)], 1u);
        o = f2o(v.w); if ((o >> 20) == bin1) atomicAdd(&g_hist2[b*4096 + ((o >> 8) & 4095)], 1u);
    }
}

__global__ void scan2_kernel() {
    int b = threadIdx.x;
    if (b >= BB) return;
    unsigned k = (unsigned)g_k[b];
    unsigned cum = g_above1[b];
    int bin = 4095;
    for (; bin >= 0; bin--) {
        unsigned c = g_hist2[b*4096 + bin];
        if (cum + c >= k) break;
        cum += c;
    }
    if (bin < 0) bin = 0;
    g_bin2[b] = (unsigned)bin;
    g_above2[b] = cum;
}

__global__ __launch_bounds__(256) void hist3_kernel(const float* __restrict__ a) {
    const float4* a4 = reinterpret_cast<const float4*>(a);
    size_t tot = (size_t)BB * NSQ / 4;
    for (size_t i = (size_t)blockIdx.x*blockDim.x + threadIdx.x; i < tot;
         i += (size_t)gridDim.x * blockDim.x) {
        int b = (int)(i >> 20);
        unsigned pfx = (g_bin1[b] << 12) | g_bin2[b];
        float4 v = a4[i];
        unsigned o;
        o = f2o(v.x); if ((o >> 8) == pfx) atomicAdd(&g_hist3[b*256 + (o & 255)], 1u);
        o = f2o(v.y); if ((o >> 8) == pfx) atomicAdd(&g_hist3[b*256 + (o & 255)], 1u);
        o = f2o(v.z); if ((o >> 8) == pfx) atomicAdd(&g_hist3[b*256 + (o & 255)], 1u);
        o = f2o(v.w); if ((o >> 8) == pfx) atomicAdd(&g_hist3[b*256 + (o & 255)], 1u);
    }
}

__global__ void scan3_kernel() {
    int b = threadIdx.x;
    if (b >= BB) return;
    unsigned k = (unsigned)g_k[b];
    unsigned cum = g_above2[b];
    int bin = 255;
    for (; bin >= 0; bin--) {
        unsigned c = g_hist3[b*256 + bin];
        if (cum + c >= k) break;
        cum += c;
    }
    if (bin < 0) bin = 0;
    g_thresh[b] = (g_bin1[b] << 20) | (g_bin2[b] << 8) | (unsigned)bin;
}

// ---------------- mask = ordered(a) >= T, plus diagonal ----------------
__global__ __launch_bounds__(256) void mask_kernel(const float* __restrict__ a, float* __restrict__ m) {
    const float4* a4 = reinterpret_cast<const float4*>(a);
    float4* m4 = reinterpret_cast<float4*>(m);
    size_t tot = (size_t)BB * NSQ / 4;
    for (size_t i = (size_t)blockIdx.x*blockDim.x + threadIdx.x; i < tot;
         i += (size_t)gridDim.x * blockDim.x) {
        int b = (int)(i >> 20);
        unsigned T = g_thresh[b];
        size_t e = (i & ((1u << 20) - 1)) * 4;      // element index within batch
        int row = (int)(e >> 11);
        int col = (int)(e & (ND - 1));
        float4 v = a4[i];
        float4 o;
        o.x = (f2o(v.x) >= T || row == col)     ? 1.0f : 0.0f;
        o.y = (f2o(v.y) >= T || row == col + 1) ? 1.0f : 0.0f;
        o.z = (f2o(v.z) >= T || row == col + 2) ? 1.0f : 0.0f;
        o.w = (f2o(v.w) >= T || row == col + 3) ? 1.0f : 0.0f;
        m4[i] = o;
    }
}

// ---------------- launch ----------------
extern "C" void kernel_launch(void* const* d_in, const int* in_sizes, int n_in,
                              void* d_out, int out_size) {
    const float* x_seq = (const float*)d_in[0];
    const float* prior = (const float*)d_in[1];
    const float* w1 = (const float*)d_in[2];
    const float* b1 = (const float*)d_in[3];
    const float* w2 = (const float*)d_in[4];
    const float* b2 = (const float*)d_in[5];
    const float* w3 = (const float*)d_in[6];
    const float* b3 = (const float*)d_in[7];
    const float* w4 = (const float*)d_in[8];
    const float* b4 = (const float*)d_in[9];
    const float* wout = (const float*)d_in[10];
    const float* bout = (const float*)d_in[11];

    float* out_mask = (float*)d_out;
    float* out_a    = out_mask + (size_t)BB * NSQ;

    zero_hists_kernel<<<64, 256>>>();
    mean_kernel<<<BB*LL, 256>>>(x_seq);
    net_kernel<<<1, 256>>>(w1, b1, w2, b2, w3, b3, w4, b4, wout, bout);
    norm_kernel<<<(BB*ND)/8, 256>>>(x_seq);
    gemm1_kernel<<<dim3(ND/128, 512/64), 256>>>(prior);
    gemm2_kernel<<<dim3(ND/128, ND/128, BB), 256>>>(out_a);
    hist1_kernel<<<dim3(128, BB), 256>>>(out_a);
    scan1_kernel<<<1, 32>>>();
    hist2_kernel<<<8192, 256>>>(out_a);
    scan2_kernel<<<1, 32>>>();
    hist3_kernel<<<8192, 256>>>(out_a);
    scan3_kernel<<<1, 32>>>();
    mask_kernel<<<8192, 256>>>(out_a, out_mask);
}

// round 3
// speedup vs baseline: 6.1037x; 6.1037x over previous
#include <cuda_runtime.h>
#include <math.h>

#define BB 8
#define LL 20
#define ND 2048           // N
#define FF 64             // F
#define NSQ (ND*ND)       // 4194304 = 2^22

// ---------------- scratch (static device, no allocation) ----------------
__device__ double g_m2[BB*LL*FF];         // per (b,l,f) mean over N (double)
__device__ int    g_k[BB];
__device__ float  g_Xn [BB*ND*FF];        // normalized x_last, [b][n][f]
__device__ float  g_Tmat[BB*FF*ND];       // t = Xn^T @ prior,  [b*64+f][k]
__device__ unsigned g_hist1[BB*4096];
__device__ unsigned g_hist2[BB*4096];
__device__ unsigned g_hist3[BB*256];
__device__ unsigned g_bin1[BB], g_bin2[BB];
__device__ unsigned g_above1[BB], g_above2[BB];
__device__ unsigned g_thresh[BB];

__device__ __forceinline__ unsigned f2o(float f) {
    unsigned u = __float_as_uint(f);
    return (u & 0x80000000u) ? ~u : (u | 0x80000000u);
}

// ---------------- zero histograms ----------------
__global__ void zero_hists_kernel() {
    int tot = BB*4096*2 + BB*256;
    for (int i = blockIdx.x*blockDim.x + threadIdx.x; i < tot; i += gridDim.x*blockDim.x) {
        if (i < BB*4096)        g_hist1[i] = 0;
        else if (i < 2*BB*4096) g_hist2[i - BB*4096] = 0;
        else                    g_hist3[i - 2*BB*4096] = 0;
    }
}

// ---------------- m2 = mean over N (double accumulation) ----------------
__global__ __launch_bounds__(256) void mean_kernel(const float* __restrict__ x_seq) {
    int bl = blockIdx.x;                    // 0..B*L-1
    int f = threadIdx.x & 63, j = threadIdx.x >> 6;   // j in 0..3
    const float* base = x_seq + (size_t)bl * ND * FF;
    double s = 0.0;
    int n0 = j * 512;
    for (int n = n0; n < n0 + 512; n++) s += (double)base[(size_t)n * FF + f];
    __shared__ double p[4][64];
    p[j][f] = s;
    __syncthreads();
    if (j == 0) {
        double t = (p[0][f] + p[1][f]) + (p[2][f] + p[3][f]);
        g_m2[bl * FF + f] = t * (1.0 / ND);
    }
}

// ---------------- tiny conv net -> k[b]  (one block per batch, float gelu) ----
__global__ __launch_bounds__(256) void net_kernel(
    const float* __restrict__ w1, const float* __restrict__ b1,
    const float* __restrict__ w2, const float* __restrict__ b2,
    const float* __restrict__ w3, const float* __restrict__ b3,
    const float* __restrict__ w4, const float* __restrict__ b4,
    const float* __restrict__ wout, const float* __restrict__ bout)
{
    __shared__ double sm[22][66];      // zero-padded (L+2) x (F+2)
    __shared__ double wsum[32][8];     // per-warp partials
    int tid = threadIdx.x;
    int lane = tid & 31, warp = tid >> 5;
    int b = blockIdx.x;

    for (int i = tid; i < 22*66; i += 256) ((double*)sm)[i] = 0.0;
    __syncthreads();
    for (int i = tid; i < LL*FF; i += 256) {
        int h = i / FF, w = i % FF;
        sm[h+1][w+1] = g_m2[(b*LL + h)*FF + w];
    }
    __syncthreads();

    double s[32];
    #pragma unroll
    for (int q = 0; q < 32; q++) s[q] = 0.0;

    for (int i = tid; i < LL*FF; i += 256) {
        int h = i / FF + 1, w = i % FF + 1;
        double c   = sm[h][w];
        double lft = sm[h][w-1], rgt = sm[h][w+1];
        double up  = sm[h-1][w], dn  = sm[h+1][w];
        double ul  = sm[h-1][w-1], ur = sm[h-1][w+1];
        double dl  = sm[h+1][w-1], dr = sm[h+1][w+1];
        #pragma unroll
        for (int ch = 0; ch < 8; ch++) {
            double v1 = (double)w1[ch]*c + (double)b1[ch];
            double v2 = (double)w2[ch*3+0]*lft + (double)w2[ch*3+1]*c + (double)w2[ch*3+2]*rgt + (double)b2[ch];
            double v3 = (double)w3[ch*3+0]*up  + (double)w3[ch*3+1]*c + (double)w3[ch*3+2]*dn  + (double)b3[ch];
            double v4 = (double)w4[ch*9+0]*ul + (double)w4[ch*9+1]*up + (double)w4[ch*9+2]*ur
                      + (double)w4[ch*9+3]*lft+ (double)w4[ch*9+4]*c  + (double)w4[ch*9+5]*rgt
                      + (double)w4[ch*9+6]*dl + (double)w4[ch*9+7]*dn + (double)w4[ch*9+8]*dr + (double)b4[ch];
            float f1 = (float)v1, f2 = (float)v2, f3 = (float)v3, f4 = (float)v4;
            s[ch]      += (double)(0.5f*f1*(1.0f + erff(f1*0.70710678f)));
            s[8  + ch] += (double)(0.5f*f2*(1.0f + erff(f2*0.70710678f)));
            s[16 + ch] += (double)(0.5f*f3*(1.0f + erff(f3*0.70710678f)));
            s[24 + ch] += (double)(0.5f*f4*(1.0f + erff(f4*0.70710678f)));
        }
    }
    // deterministic warp-tree reduction
    #pragma unroll
    for (int q = 0; q < 32; q++) {
        double v = s[q];
        #pragma unroll
        for (int o = 16; o; o >>= 1) v += __shfl_down_sync(0xffffffffu, v, o);
        if (lane == 0) wsum[q][warp] = v;
    }
    __syncthreads();
    if (tid == 0) {
        double logit = (double)bout[0];
        for (int q = 0; q < 32; q++) {
            double t = 0.0;
            for (int w = 0; w < 8; w++) t += wsum[q][w];   // fixed order
            logit += (t * (1.0/(LL*FF))) * (double)wout[q];
        }
        double sig  = 1.0 / (1.0 + exp(-logit));
        double keep = 0.2 * sig;
        if (keep < 0.02) keep = 0.02;
        if (keep > 1.0)  keep = 1.0;
        // replicate reference fp32 quantization: fp32(keep) * fp32(NSQ), ceil
        float kf = __fmul_rn((float)keep, 4194304.0f);
        int k = (int)ceilf(kf);
        if (k < 1) k = 1;
        if (k > NSQ) k = NSQ;
        g_k[b] = k;
    }
}

// ---------------- normalize last slice (double), write Xn only --------------
__global__ __launch_bounds__(256) void norm_kernel(const float* __restrict__ x_seq) {
    int warp = (blockIdx.x*blockDim.x + threadIdx.x) >> 5;
    int lane = threadIdx.x & 31;
    if (warp >= BB*ND) return;
    int b = warp >> 11, n = warp & (ND-1);
    const float* row = x_seq + ((size_t)(b*LL + (LL-1)) * ND + n) * FF;
    float v0 = row[lane], v1 = row[lane + 32];
    double ss = (double)v0*(double)v0 + (double)v1*(double)v1;
    #pragma unroll
    for (int o = 16; o; o >>= 1) ss += __shfl_xor_sync(0xffffffffu, ss, o);
    double d = sqrt(ss);
    if (d < 1e-12) d = 1e-12;
    float y0 = (float)((double)v0 / d), y1 = (float)((double)v1 / d);
    size_t rb = (size_t)(b*ND + n) * FF;
    g_Xn[rb + lane]      = y0;
    g_Xn[rb + lane + 32] = y1;
}

// ---------------- GEMM1: Tmat(512x2048) = XnT(512x2048) @ prior(2048x2048) ----
// A read transposed from g_Xn; per-BK local acc + Kahan flush (accuracy-critical)
__global__ __launch_bounds__(256) void gemm1_kernel(const float* __restrict__ Bm) {
    const int BM = 64, BN = 128, BK = 16;
    __shared__ float As[BK][BM+1];
    __shared__ __align__(16) float Bs[BK][BN];
    int tx = threadIdx.x & 15, ty = threadIdx.x >> 4;
    int b = blockIdx.y;                     // 8 blocks in y: one batch each (64 f-rows)
    int bm0 = b * BM, bn0 = blockIdx.x * BN;
    float acc[4][8], comp[4][8];
    #pragma unroll
    for (int i = 0; i < 4; i++)
        #pragma unroll
        for (int j = 0; j < 8; j++) { acc[i][j] = 0.f; comp[i][j] = 0.f; }

    for (int k0 = 0; k0 < ND; k0 += BK) {
        #pragma unroll
        for (int r = 0; r < 4; r++) {
            int idx = threadIdx.x + r*256, f = idx & 63, kk = idx >> 6;
            // XnT[bm0+f][k0+kk] = Xn[b][k0+kk][f]
            As[kk][f] = g_Xn[((size_t)b*ND + k0 + kk)*FF + f];
        }
        #pragma unroll
        for (int r = 0; r < 8; r++) {
            int idx = threadIdx.x + r*256, kk = idx >> 7, col = idx & 127;
            Bs[kk][col] = Bm[(size_t)(k0 + kk) * ND + bn0 + col];
        }
        __syncthreads();
        float loc[4][8];
        #pragma unroll
        for (int i = 0; i < 4; i++)
            #pragma unroll
            for (int j = 0; j < 8; j++) loc[i][j] = 0.f;
        #pragma unroll
        for (int kk = 0; kk < BK; kk++) {
            float a0 = As[kk][ty*4+0], a1 = As[kk][ty*4+1];
            float a2 = As[kk][ty*4+2], a3 = As[kk][ty*4+3];
            float4 q0 = *reinterpret_cast<const float4*>(&Bs[kk][tx*8]);
            float4 q1 = *reinterpret_cast<const float4*>(&Bs[kk][tx*8+4]);
            float bb[8] = {q0.x,q0.y,q0.z,q0.w,q1.x,q1.y,q1.z,q1.w};
            #pragma unroll
            for (int j = 0; j < 8; j++) {
                loc[0][j] = __fmaf_rn(a0, bb[j], loc[0][j]);
                loc[1][j] = __fmaf_rn(a1, bb[j], loc[1][j]);
                loc[2][j] = __fmaf_rn(a2, bb[j], loc[2][j]);
                loc[3][j] = __fmaf_rn(a3, bb[j], loc[3][j]);
            }
        }
        // Kahan flush: acc += loc with compensation
        #pragma unroll
        for (int i = 0; i < 4; i++)
            #pragma unroll
            for (int j = 0; j < 8; j++) {
                float y = __fadd_rn(loc[i][j], -comp[i][j]);
                float t = __fadd_rn(acc[i][j], y);
                comp[i][j] = __fadd_rn(__fadd_rn(t, -acc[i][j]), -y);
                acc[i][j] = t;
            }
        __syncthreads();
    }
    #pragma unroll
    for (int i = 0; i < 4; i++)
        #pragma unroll
        for (int j = 0; j < 8; j++)
            g_Tmat[(size_t)(bm0 + ty*4 + i) * ND + bn0 + tx*8 + j] = acc[i][j];
}

// ---------------- GEMM2 (+fused hist1): a_b = Xn_b(2048x64) @ t_b(64x2048) ---
// 512 threads, per-thread 4x8; identical per-element summation order to R2.
__global__ __launch_bounds__(512) void gemm2_kernel(float* __restrict__ outA) {
    const int BM = 128, BN = 128, BK = 16;
    __shared__ float As[BK][BM+1];
    __shared__ __align__(16) float Bs[BK][BN];
    __shared__ unsigned sh_hist[4096];
    int b = blockIdx.z;
    const float* A  = g_Xn   + (size_t)b * ND * FF;
    const float* Bmm= g_Tmat + (size_t)b * FF * ND;
    float* C = outA + (size_t)b * NSQ;
    int tid = threadIdx.x;
    int tx = tid & 15, ty = tid >> 4;     // ty 0..31
    int bm0 = blockIdx.y * BM, bn0 = blockIdx.x * BN;

    for (int i = tid; i < 4096; i += 512) sh_hist[i] = 0;

    float acc[4][8];
    #pragma unroll
    for (int i = 0; i < 4; i++)
        #pragma unroll
        for (int j = 0; j < 8; j++) acc[i][j] = 0.f;

    for (int k0 = 0; k0 < FF; k0 += BK) {
        #pragma unroll
        for (int r = 0; r < 4; r++) {
            int idx = tid + r*512, m = idx >> 4, kk = idx & 15;
            As[kk][m] = A[(size_t)(bm0 + m) * FF + k0 + kk];
        }
        #pragma unroll
        for (int r = 0; r < 4; r++) {
            int idx = tid + r*512, kk = idx >> 7, col = idx & 127;
            Bs[kk][col] = Bmm[(size_t)(k0 + kk) * ND + bn0 + col];
        }
        __syncthreads();
        float loc[4][8];
        #pragma unroll
        for (int i = 0; i < 4; i++)
            #pragma unroll
            for (int j = 0; j < 8; j++) loc[i][j] = 0.f;
        #pragma unroll
        for (int kk = 0; kk < BK; kk++) {
            float av[4];
            #pragma unroll
            for (int i = 0; i < 4; i++) av[i] = As[kk][ty*4 + i];
            float4 q0 = *reinterpret_cast<const float4*>(&Bs[kk][tx*8]);
            float4 q1 = *reinterpret_cast<const float4*>(&Bs[kk][tx*8+4]);
            float bb[8] = {q0.x,q0.y,q0.z,q0.w,q1.x,q1.y,q1.z,q1.w};
            #pragma unroll
            for (int i = 0; i < 4; i++)
                #pragma unroll
                for (int j = 0; j < 8; j++)
                    loc[i][j] = __fmaf_rn(av[i], bb[j], loc[i][j]);
        }
        #pragma unroll
        for (int i = 0; i < 4; i++)
            #pragma unroll
            for (int j = 0; j < 8; j++)
                acc[i][j] = __fadd_rn(acc[i][j], loc[i][j]);
        __syncthreads();
    }
    // epilogue: store + warp-aggregated histogram (top 12 ordered bits)
    int lane = tid & 31;
    #pragma unroll
    for (int i = 0; i < 4; i++) {
        float4 o0 = make_float4(acc[i][0], acc[i][1], acc[i][2], acc[i][3]);
        float4 o1 = make_float4(acc[i][4], acc[i][5], acc[i][6], acc[i][7]);
        size_t rowbase = (size_t)(bm0 + ty*4 + i) * ND + bn0 + tx*8;
        *reinterpret_cast<float4*>(&C[rowbase])     = o0;
        *reinterpret_cast<float4*>(&C[rowbase + 4]) = o1;
        #pragma unroll
        for (int j = 0; j < 8; j++) {
            unsigned bin = f2o(acc[i][j]) >> 20;
            unsigned mm = __match_any_sync(0xffffffffu, bin);
            if (lane == (__ffs(mm) - 1)) atomicAdd(&sh_hist[bin], (unsigned)__popc(mm));
        }
    }
    __syncthreads();
    for (int i = tid; i < 4096; i += 512) {
        unsigned c = sh_hist[i];
        if (c) atomicAdd(&g_hist1[b*4096 + i], c);
    }
}

// ---------------- parallel block select over a histogram --------------------
// Replicates: cum=prev; for bin=NB-1..0 { c=h[bin]; if (cum+c>=k) break; cum+=c; }
__device__ __forceinline__ void block_select(const unsigned* __restrict__ h, int NB,
                                             unsigned prev, unsigned k,
                                             unsigned* ps, unsigned* res) {
    int t = threadIdx.x;
    int CH = NB >> 8;                    // bins per thread (descending order)
    unsigned csum = 0;
    for (int j = 0; j < CH; j++) csum += h[NB - 1 - (t*CH + j)];
    ps[t] = csum;
    __syncthreads();
    #pragma unroll
    for (int off = 1; off < 256; off <<= 1) {
        unsigned v = (t >= off) ? ps[t - off] : 0u;
        __syncthreads();
        ps[t] += v;
        __syncthreads();
    }
    unsigned excl = ps[t] - csum;
    unsigned cum = prev + excl;
    if (t == 0) { res[0] = 0u; res[1] = prev; }   // fallback (cannot trigger)
    __syncthreads();
    if (cum < k && cum + csum >= k) {             // crossing is inside my chunk
        for (int j = 0; j < CH; j++) {
            int bin = NB - 1 - (t*CH + j);
            unsigned c = h[bin];
            if (cum + c >= k) { res[0] = (unsigned)bin; res[1] = cum; break; }
            cum += c;
        }
    }
    __syncthreads();
}

__global__ __launch_bounds__(256) void scan1_kernel() {
    __shared__ unsigned ps[256]; __shared__ unsigned res[2];
    int b = blockIdx.x;
    block_select(g_hist1 + b*4096, 4096, 0u, (unsigned)g_k[b], ps, res);
    if (threadIdx.x == 0) { g_bin1[b] = res[0]; g_above1[b] = res[1]; }
}
__global__ __launch_bounds__(256) void scan2_kernel() {
    __shared__ unsigned ps[256]; __shared__ unsigned res[2];
    int b = blockIdx.x;
    block_select(g_hist2 + b*4096, 4096, g_above1[b], (unsigned)g_k[b], ps, res);
    if (threadIdx.x == 0) { g_bin2[b] = res[0]; g_above2[b] = res[1]; }
}
__global__ __launch_bounds__(256) void scan3_kernel() {
    __shared__ unsigned ps[256]; __shared__ unsigned res[2];
    int b = blockIdx.x;
    block_select(g_hist3 + b*256, 256, g_above2[b], (unsigned)g_k[b], ps, res);
    if (threadIdx.x == 0)
        g_thresh[b] = (g_bin1[b] << 20) | (g_bin2[b] << 8) | res[0];
}

// ---------------- refinement histograms (full-pass, rare atomics) -----------
__global__ __launch_bounds__(256) void hist2_kernel(const float* __restrict__ a) {
    const float4* a4 = reinterpret_cast<const float4*>(a);
    size_t tot = (size_t)BB * NSQ / 4;
    for (size_t i = (size_t)blockIdx.x*blockDim.x + threadIdx.x; i < tot;
         i += (size_t)gridDim.x * blockDim.x) {
        int b = (int)(i >> 20);
        unsigned bin1 = g_bin1[b];
        float4 v = a4[i];
        unsigned o;
        o = f2o(v.x); if ((o >> 20) == bin1) atomicAdd(&g_hist2[b*4096 + ((o >> 8) & 4095)], 1u);
        o = f2o(v.y); if ((o >> 20) == bin1) atomicAdd(&g_hist2[b*4096 + ((o >> 8) & 4095)], 1u);
        o = f2o(v.z); if ((o >> 20) == bin1) atomicAdd(&g_hist2[b*4096 + ((o >> 8) & 4095)], 1u);
        o = f2o(v.w); if ((o >> 20) == bin1) atomicAdd(&g_hist2[b*4096 + ((o >> 8) & 4095)], 1u);
    }
}

__global__ __launch_bounds__(256) void hist3_kernel(const float* __restrict__ a) {
    const float4* a4 = reinterpret_cast<const float4*>(a);
    size_t tot = (size_t)BB * NSQ / 4;
    for (size_t i = (size_t)blockIdx.x*blockDim.x + threadIdx.x; i < tot;
         i += (size_t)gridDim.x * blockDim.x) {
        int b = (int)(i >> 20);
        unsigned pfx = (g_bin1[b] << 12) | g_bin2[b];
        float4 v = a4[i];
        unsigned o;
        o = f2o(v.x); if ((o >> 8) == pfx) atomicAdd(&g_hist3[b*256 + (o & 255)], 1u);
        o = f2o(v.y); if ((o >> 8) == pfx) atomicAdd(&g_hist3[b*256 + (o & 255)], 1u);
        o = f2o(v.z); if ((o >> 8) == pfx) atomicAdd(&g_hist3[b*256 + (o & 255)], 1u);
        o = f2o(v.w); if ((o >> 8) == pfx) atomicAdd(&g_hist3[b*256 + (o & 255)], 1u);
    }
}

// ---------------- mask = ordered(a) >= T, plus diagonal ----------------
__global__ __launch_bounds__(256) void mask_kernel(const float* __restrict__ a, float* __restrict__ m) {
    const float4* a4 = reinterpret_cast<const float4*>(a);
    float4* m4 = reinterpret_cast<float4*>(m);
    size_t tot = (size_t)BB * NSQ / 4;
    for (size_t i = (size_t)blockIdx.x*blockDim.x + threadIdx.x; i < tot;
         i += (size_t)gridDim.x * blockDim.x) {
        int b = (int)(i >> 20);
        unsigned T = g_thresh[b];
        size_t e = (i & ((1u << 20) - 1)) * 4;      // element index within batch
        int row = (int)(e >> 11);
        int col = (int)(e & (ND - 1));
        float4 v = a4[i];
        float4 o;
        o.x = (f2o(v.x) >= T || row == col)     ? 1.0f : 0.0f;
        o.y = (f2o(v.y) >= T || row == col + 1) ? 1.0f : 0.0f;
        o.z = (f2o(v.z) >= T || row == col + 2) ? 1.0f : 0.0f;
        o.w = (f2o(v.w) >= T || row == col + 3) ? 1.0f : 0.0f;
        m4[i] = o;
    }
}

// ---------------- launch ----------------
extern "C" void kernel_launch(void* const* d_in, const int* in_sizes, int n_in,
                              void* d_out, int out_size) {
    const float* x_seq = (const float*)d_in[0];
    const float* prior = (const float*)d_in[1];
    const float* w1 = (const float*)d_in[2];
    const float* b1 = (const float*)d_in[3];
    const float* w2 = (const float*)d_in[4];
    const float* b2 = (const float*)d_in[5];
    const float* w3 = (const float*)d_in[6];
    const float* b3 = (const float*)d_in[7];
    const float* w4 = (const float*)d_in[8];
    const float* b4 = (const float*)d_in[9];
    const float* wout = (const float*)d_in[10];
    const float* bout = (const float*)d_in[11];

    float* out_mask = (float*)d_out;
    float* out_a    = out_mask + (size_t)BB * NSQ;

    zero_hists_kernel<<<64, 256>>>();
    mean_kernel<<<BB*LL, 256>>>(x_seq);
    net_kernel<<<BB, 256>>>(w1, b1, w2, b2, w3, b3, w4, b4, wout, bout);
    norm_kernel<<<(BB*ND)/8, 256>>>(x_seq);
    gemm1_kernel<<<dim3(ND/128, BB), 256>>>(prior);
    gemm2_kernel<<<dim3(ND/128, ND/128, BB), 512>>>(out_a);
    scan1_kernel<<<BB, 256>>>();
    hist2_kernel<<<8192, 256>>>(out_a);
    scan2_kernel<<<BB, 256>>>();
    hist3_kernel<<<8192, 256>>>(out_a);
    scan3_kernel<<<BB, 256>>>();
    mask_kernel<<<8192, 256>>>(out_a, out_mask);
}